// round 1
// baseline (speedup 1.0000x reference)
#include <cuda_runtime.h>
#include <math.h>

#define BB 32
#define TT 64
#define SS 64
#define HH 1024
#define EE 512
#define VV 32000
#define G4H 4096

// ---------------- device scratch (static, no runtime alloc) ----------------
__device__ float g_gi[TT * BB * G4H];     // precomputed x@W_ih^T + b_ih + b_hh   (32 MB)
__device__ float g_hbuf[2][BB * HH];      // ping-pong h
__device__ float g_c[BB * HH];            // cell state (in-place, disjoint per block)
__device__ float g_ctx[BB * HH];          // attention context per step
__device__ float g_barout[TT * BB * HH];  // tanh(fc1(...)) rows m = t*B+b       (8 MB)

// ---------------- init h,c from inputs ----------------
__global__ void init_hc(const float* __restrict__ h0, const float* __restrict__ c0) {
    int i = blockIdx.x * 256 + threadIdx.x;   // grid 128 x 256 = 32768 exact
    g_hbuf[0][i] = h0[i];
    g_c[i] = c0[i];
}

// ---------------- GEMM1: gi[m][n] = sum_k emb[vid[m]][k] * W_ih[n][k] + b_ih[n]+b_hh[n]
// M=2048 (m=t*B+b), N=4096, K=512. 128x128 tile, BK=16, 256 threads, 8x8 microtile.
__global__ void embed_gemm(const int* __restrict__ inputs, const float* __restrict__ emb,
                           const float* __restrict__ W, const float* __restrict__ b1,
                           const float* __restrict__ b2) {
    __shared__ float As[16][128];
    __shared__ float Bs[16][128];
    __shared__ int vid[128];
    const int tid = threadIdx.x;
    const int mBase = blockIdx.y * 128, nBase = blockIdx.x * 128;
    if (tid < 128) {
        int m = mBase + tid;                 // m = t*32 + b
        vid[tid] = inputs[(m & 31) * TT + (m >> 5)];  // inputs[b][t]
    }
    const int tx = tid & 15, ty = tid >> 4;
    const int lrow = tid >> 1, lcol = (tid & 1) * 8;
    float acc[8][8] = {};
    __syncthreads();
    const float* aSrc = emb + (long)vid[lrow] * EE + lcol;
    const float* bSrc = W + (long)(nBase + lrow) * EE + lcol;
    for (int k0 = 0; k0 < EE; k0 += 16) {
        float4 a0 = *(const float4*)(aSrc + k0);
        float4 a1 = *(const float4*)(aSrc + k0 + 4);
        float4 w0 = *(const float4*)(bSrc + k0);
        float4 w1 = *(const float4*)(bSrc + k0 + 4);
        As[lcol + 0][lrow] = a0.x; As[lcol + 1][lrow] = a0.y;
        As[lcol + 2][lrow] = a0.z; As[lcol + 3][lrow] = a0.w;
        As[lcol + 4][lrow] = a1.x; As[lcol + 5][lrow] = a1.y;
        As[lcol + 6][lrow] = a1.z; As[lcol + 7][lrow] = a1.w;
        Bs[lcol + 0][lrow] = w0.x; Bs[lcol + 1][lrow] = w0.y;
        Bs[lcol + 2][lrow] = w0.z; Bs[lcol + 3][lrow] = w0.w;
        Bs[lcol + 4][lrow] = w1.x; Bs[lcol + 5][lrow] = w1.y;
        Bs[lcol + 6][lrow] = w1.z; Bs[lcol + 7][lrow] = w1.w;
        __syncthreads();
#pragma unroll
        for (int k = 0; k < 16; k++) {
            float a[8], bvals[8];
            *(float4*)&a[0] = *(const float4*)&As[k][ty * 8];
            *(float4*)&a[4] = *(const float4*)&As[k][ty * 8 + 4];
            *(float4*)&bvals[0] = *(const float4*)&Bs[k][tx * 8];
            *(float4*)&bvals[4] = *(const float4*)&Bs[k][tx * 8 + 4];
#pragma unroll
            for (int i = 0; i < 8; i++)
#pragma unroll
                for (int j = 0; j < 8; j++) acc[i][j] += a[i] * bvals[j];
        }
        __syncthreads();
    }
#pragma unroll
    for (int i = 0; i < 8; i++) {
        int m = mBase + ty * 8 + i;
        float* o = g_gi + (long)m * G4H + nBase + tx * 8;
#pragma unroll
        for (int j = 0; j < 8; j++) {
            int n = nBase + tx * 8 + j;
            o[j] = acc[i][j] + b1[n] + b2[n];
        }
    }
}

// ---------------- per-step LSTM: gates = gi[t] + h@W_hh^T, then elementwise.
// grid 128 blocks (8 hidden indices j each, all 4 gates), 128 threads.
__global__ void lstm_step(int t, const float* __restrict__ Whh) {
    __shared__ float hs[32][36];   // [k][b]
    __shared__ float ws[32][36];   // [k][c], c = jl*4 + gate
    __shared__ float Gm[32][33];   // [b][c] gate pre-activations
    const int tid = threadIdx.x;
    const int jbase = blockIdx.x * 8;
    const int bq = tid & 7, cq = tid >> 3;  // thread: 4 b's, 2 cols
    const float* __restrict__ hin = g_hbuf[t & 1];
    float a00 = 0, a01 = 0, a10 = 0, a11 = 0, a20 = 0, a21 = 0, a30 = 0, a31 = 0;
    for (int kt = 0; kt < HH; kt += 32) {
#pragma unroll
        for (int r = 0; r < 8; r++) {
            int i = r * 128 + tid;
            int bb = i >> 5, k = i & 31;
            hs[k][bb] = hin[bb * HH + kt + k];
        }
#pragma unroll
        for (int r = 0; r < 8; r++) {
            int i = r * 128 + tid;
            int cc = i >> 5, k = i & 31;
            ws[k][cc] = Whh[(long)((cc & 3) * HH + jbase + (cc >> 2)) * HH + kt + k];
        }
        __syncthreads();
#pragma unroll
        for (int k = 0; k < 32; k++) {
            float4 hv = *(const float4*)&hs[k][bq * 4];
            float2 wv = *(const float2*)&ws[k][cq * 2];
            a00 += hv.x * wv.x; a01 += hv.x * wv.y;
            a10 += hv.y * wv.x; a11 += hv.y * wv.y;
            a20 += hv.z * wv.x; a21 += hv.z * wv.y;
            a30 += hv.w * wv.x; a31 += hv.w * wv.y;
        }
        __syncthreads();
    }
    Gm[bq * 4 + 0][cq * 2] = a00; Gm[bq * 4 + 0][cq * 2 + 1] = a01;
    Gm[bq * 4 + 1][cq * 2] = a10; Gm[bq * 4 + 1][cq * 2 + 1] = a11;
    Gm[bq * 4 + 2][cq * 2] = a20; Gm[bq * 4 + 2][cq * 2 + 1] = a21;
    Gm[bq * 4 + 3][cq * 2] = a30; Gm[bq * 4 + 3][cq * 2 + 1] = a31;
    __syncthreads();
    float* __restrict__ hout = g_hbuf[(t + 1) & 1];
    const float* gi = g_gi + (long)(t * BB) * G4H;
#pragma unroll
    for (int r = 0; r < 2; r++) {
        int i = r * 128 + tid;
        int bb = i & 31, jl = i >> 5;
        int j = jbase + jl;
        const float* gr = gi + (long)bb * G4H;
        float xi = Gm[bb][jl * 4 + 0] + gr[j];
        float xf = Gm[bb][jl * 4 + 1] + gr[HH + j];
        float xg = Gm[bb][jl * 4 + 2] + gr[2 * HH + j];
        float xo = Gm[bb][jl * 4 + 3] + gr[3 * HH + j];
        float ig = 1.f / (1.f + expf(-xi));
        float fg = 1.f / (1.f + expf(-xf));
        float gg = tanhf(xg);
        float og = 1.f / (1.f + expf(-xo));
        float cn = fg * g_c[bb * HH + j] + ig * gg;
        g_c[bb * HH + j] = cn;
        hout[bb * HH + j] = og * tanhf(cn);
    }
}

// ---------------- per-step attention: one block per batch element ----------------
__global__ void attn_step(int t, const float* __restrict__ hiddens) {
    const int b = blockIdx.x;
    __shared__ float hsh[HH];
    __shared__ float sc[SS];
    const int tid = threadIdx.x;
    const int lane = tid & 31, w = tid >> 5;
    const float* __restrict__ h = g_hbuf[(t + 1) & 1];
    for (int i = tid; i < HH; i += 256) hsh[i] = h[b * HH + i];
    __syncthreads();
    for (int s = w; s < SS; s += 8) {
        const float* e = hiddens + ((long)s * BB + b) * HH;
        float a = 0.f;
#pragma unroll 8
        for (int k = lane; k < HH; k += 32) a += e[k] * hsh[k];
        for (int o = 16; o; o >>= 1) a += __shfl_down_sync(0xFFFFFFFFu, a, o);
        if (!lane) sc[s] = a;
    }
    __syncthreads();
    if (tid < 32) {
        float v0 = sc[tid], v1 = sc[tid + 32];
        float m = fmaxf(v0, v1);
        for (int o = 16; o; o >>= 1) m = fmaxf(m, __shfl_xor_sync(0xFFFFFFFFu, m, o));
        float e0 = expf(v0 - m), e1 = expf(v1 - m);
        float sm = e0 + e1;
        for (int o = 16; o; o >>= 1) sm += __shfl_xor_sync(0xFFFFFFFFu, sm, o);
        sc[tid] = e0 / sm; sc[tid + 32] = e1 / sm;
    }
    __syncthreads();
    int h0 = tid * 4;
    float4 acc = make_float4(0.f, 0.f, 0.f, 0.f);
    for (int s = 0; s < SS; s++) {
        float a = sc[s];
        float4 e = *(const float4*)(hiddens + ((long)s * BB + b) * HH + h0);
        acc.x += a * e.x; acc.y += a * e.y; acc.z += a * e.z; acc.w += a * e.w;
    }
    *(float4*)(g_ctx + b * HH + h0) = acc;
}

// ---------------- per-step fc1: barout[t*B+b][j] = tanh([h|ctx]@fc1_W^T + fc1_b)
// grid 64 blocks (16 j each), 128 threads.
__global__ void fc1_step(int t, const float* __restrict__ W, const float* __restrict__ bias) {
    __shared__ float as[32][36];  // [k][b]
    __shared__ float ws[32][17];  // [k][jl]
    const int tid = threadIdx.x;
    const int jb = blockIdx.x * 16;
    const int bq = tid & 7, cq = tid >> 3;  // 4 b's, 1 col
    const float* __restrict__ h = g_hbuf[(t + 1) & 1];
    float acc[4] = {0.f, 0.f, 0.f, 0.f};
    for (int kt = 0; kt < 2048; kt += 32) {
        const float* A = (kt < HH) ? h : g_ctx;
        int kb = kt & (HH - 1);
#pragma unroll
        for (int r = 0; r < 8; r++) {
            int i = r * 128 + tid;
            int bb = i >> 5, k = i & 31;
            as[k][bb] = A[bb * HH + kb + k];
        }
#pragma unroll
        for (int r = 0; r < 4; r++) {
            int i = r * 128 + tid;
            int jl = i >> 5, k = i & 31;
            ws[k][jl] = W[(long)(jb + jl) * 2048 + kt + k];
        }
        __syncthreads();
#pragma unroll
        for (int k = 0; k < 32; k++) {
            float4 av = *(const float4*)&as[k][bq * 4];
            float wv = ws[k][cq];
            acc[0] += av.x * wv; acc[1] += av.y * wv;
            acc[2] += av.z * wv; acc[3] += av.w * wv;
        }
        __syncthreads();
    }
    int j = jb + cq;
    float bj = bias[j];
#pragma unroll
    for (int i = 0; i < 4; i++) {
        int bb = bq * 4 + i;
        g_barout[(long)(t * BB + bb) * HH + j] = tanhf(acc[i] + bj);
    }
}

// ---------------- fc2: out[b][t][v] = barout[t*B+b] . fc2_W[v] + fc2_b[v]
// M=2048, N=32000, K=1024. Same 128x128 SGEMM.
__global__ void fc2_gemm(const float* __restrict__ W, const float* __restrict__ bias,
                         float* __restrict__ out) {
    __shared__ float As[16][128];
    __shared__ float Bs[16][128];
    const int tid = threadIdx.x;
    const int mBase = blockIdx.y * 128, nBase = blockIdx.x * 128;
    const int tx = tid & 15, ty = tid >> 4;
    const int lrow = tid >> 1, lcol = (tid & 1) * 8;
    float acc[8][8] = {};
    const float* aSrc = g_barout + (long)(mBase + lrow) * HH + lcol;
    const float* bSrc = W + (long)(nBase + lrow) * HH + lcol;
    for (int k0 = 0; k0 < HH; k0 += 16) {
        float4 a0 = *(const float4*)(aSrc + k0);
        float4 a1 = *(const float4*)(aSrc + k0 + 4);
        float4 w0 = *(const float4*)(bSrc + k0);
        float4 w1 = *(const float4*)(bSrc + k0 + 4);
        As[lcol + 0][lrow] = a0.x; As[lcol + 1][lrow] = a0.y;
        As[lcol + 2][lrow] = a0.z; As[lcol + 3][lrow] = a0.w;
        As[lcol + 4][lrow] = a1.x; As[lcol + 5][lrow] = a1.y;
        As[lcol + 6][lrow] = a1.z; As[lcol + 7][lrow] = a1.w;
        Bs[lcol + 0][lrow] = w0.x; Bs[lcol + 1][lrow] = w0.y;
        Bs[lcol + 2][lrow] = w0.z; Bs[lcol + 3][lrow] = w0.w;
        Bs[lcol + 4][lrow] = w1.x; Bs[lcol + 5][lrow] = w1.y;
        Bs[lcol + 6][lrow] = w1.z; Bs[lcol + 7][lrow] = w1.w;
        __syncthreads();
#pragma unroll
        for (int k = 0; k < 16; k++) {
            float a[8], bvals[8];
            *(float4*)&a[0] = *(const float4*)&As[k][ty * 8];
            *(float4*)&a[4] = *(const float4*)&As[k][ty * 8 + 4];
            *(float4*)&bvals[0] = *(const float4*)&Bs[k][tx * 8];
            *(float4*)&bvals[4] = *(const float4*)&Bs[k][tx * 8 + 4];
#pragma unroll
            for (int i = 0; i < 8; i++)
#pragma unroll
                for (int j = 0; j < 8; j++) acc[i][j] += a[i] * bvals[j];
        }
        __syncthreads();
    }
#pragma unroll
    for (int i = 0; i < 8; i++) {
        int m = mBase + ty * 8 + i;
        int t = m >> 5, bb = m & 31;
        float* o = out + ((long)bb * TT + t) * VV + nBase + tx * 8;
#pragma unroll
        for (int j = 0; j < 8; j++) o[j] = acc[i][j] + bias[nBase + tx * 8 + j];
    }
}

// ---------------- launch ----------------
extern "C" void kernel_launch(void* const* d_in, const int* in_sizes, int n_in,
                              void* d_out, int out_size) {
    const int*   inputs  = (const int*)d_in[0];
    const float* hiddens = (const float*)d_in[1];
    const float* hidden  = (const float*)d_in[2];
    const float* cell    = (const float*)d_in[3];
    const float* emb     = (const float*)d_in[4];
    const float* W_ih    = (const float*)d_in[5];
    const float* b_ih    = (const float*)d_in[6];
    const float* W_hh    = (const float*)d_in[7];
    const float* b_hh    = (const float*)d_in[8];
    const float* fc1_W   = (const float*)d_in[9];
    const float* fc1_b   = (const float*)d_in[10];
    const float* fc2_W   = (const float*)d_in[11];
    const float* fc2_b   = (const float*)d_in[12];
    float* out = (float*)d_out;

    init_hc<<<128, 256>>>(hidden, cell);
    embed_gemm<<<dim3(G4H / 128, (TT * BB) / 128), 256>>>(inputs, emb, W_ih, b_ih, b_hh);
    for (int t = 0; t < TT; t++) {
        lstm_step<<<128, 128>>>(t, W_hh);
        attn_step<<<BB, 256>>>(t, hiddens);
        fc1_step<<<64, 128>>>(t, fc1_W, fc1_b);
    }
    fc2_gemm<<<dim3(VV / 128, (TT * BB) / 128), 256>>>(fc2_W, fc2_b, out);
}

// round 2
// speedup vs baseline: 2.8352x; 2.8352x over previous
#include <cuda_runtime.h>
#include <math.h>
#include <stdint.h>

#define BB 32
#define TT 64
#define SS 64
#define HH 1024
#define EE 512
#define VV 32000
#define G4H 4096
#define KSL 8
#define KSF 16

// ---------------- device scratch ----------------
__device__ float g_gi[TT * BB * G4H];            // x@W_ih^T + b_ih + b_hh (32MB)
__device__ float g_hbuf[2][BB * HH];
__device__ float g_c[BB * HH];
__device__ float g_ctx[BB * HH];
__device__ float g_lpart[KSL * BB * G4H];        // lstm split-K partials (4MB)
__device__ float g_fpart[(long)TT * KSF * BB * HH]; // fc1 split-K partials (128MB)
__device__ float g_barout[TT * BB * HH];         // tanh(fc1) rows m=t*B+b (8MB)

__global__ void init_hc(const float* __restrict__ h0, const float* __restrict__ c0) {
    int i = blockIdx.x * 256 + threadIdx.x;
    g_hbuf[0][i] = h0[i];
    g_c[i] = c0[i];
}

// ---------------- GEMM1: gi = emb[vid] @ W_ih^T + b_ih + b_hh ----------------
__global__ void embed_gemm(const int* __restrict__ inputs, const float* __restrict__ emb,
                           const float* __restrict__ W, const float* __restrict__ b1,
                           const float* __restrict__ b2) {
    __shared__ float As[16][128];
    __shared__ float Bs[16][128];
    __shared__ int vid[128];
    const int tid = threadIdx.x;
    const int mBase = blockIdx.y * 128, nBase = blockIdx.x * 128;
    if (tid < 128) {
        int m = mBase + tid;
        vid[tid] = inputs[(m & 31) * TT + (m >> 5)];
    }
    const int tx = tid & 15, ty = tid >> 4;
    const int lrow = tid >> 1, lcol = (tid & 1) * 8;
    float acc[8][8] = {};
    __syncthreads();
    const float* aSrc = emb + (long)vid[lrow] * EE + lcol;
    const float* bSrc = W + (long)(nBase + lrow) * EE + lcol;
    for (int k0 = 0; k0 < EE; k0 += 16) {
        float4 a0 = *(const float4*)(aSrc + k0);
        float4 a1 = *(const float4*)(aSrc + k0 + 4);
        float4 w0 = *(const float4*)(bSrc + k0);
        float4 w1 = *(const float4*)(bSrc + k0 + 4);
        As[lcol + 0][lrow] = a0.x; As[lcol + 1][lrow] = a0.y;
        As[lcol + 2][lrow] = a0.z; As[lcol + 3][lrow] = a0.w;
        As[lcol + 4][lrow] = a1.x; As[lcol + 5][lrow] = a1.y;
        As[lcol + 6][lrow] = a1.z; As[lcol + 7][lrow] = a1.w;
        Bs[lcol + 0][lrow] = w0.x; Bs[lcol + 1][lrow] = w0.y;
        Bs[lcol + 2][lrow] = w0.z; Bs[lcol + 3][lrow] = w0.w;
        Bs[lcol + 4][lrow] = w1.x; Bs[lcol + 5][lrow] = w1.y;
        Bs[lcol + 6][lrow] = w1.z; Bs[lcol + 7][lrow] = w1.w;
        __syncthreads();
#pragma unroll
        for (int k = 0; k < 16; k++) {
            float a[8], bv[8];
            *(float4*)&a[0] = *(const float4*)&As[k][ty * 8];
            *(float4*)&a[4] = *(const float4*)&As[k][ty * 8 + 4];
            *(float4*)&bv[0] = *(const float4*)&Bs[k][tx * 8];
            *(float4*)&bv[4] = *(const float4*)&Bs[k][tx * 8 + 4];
#pragma unroll
            for (int i = 0; i < 8; i++)
#pragma unroll
                for (int j = 0; j < 8; j++) acc[i][j] += a[i] * bv[j];
        }
        __syncthreads();
    }
#pragma unroll
    for (int i = 0; i < 8; i++) {
        int m = mBase + ty * 8 + i;
        float* o = g_gi + (long)m * G4H + nBase + tx * 8;
#pragma unroll
        for (int j = 0; j < 8; j++) {
            int n = nBase + tx * 8 + j;
            o[j] = acc[i][j] + b1[n] + b2[n];
        }
    }
}

// ---------------- lstm_gemm: partial[ks][b][c] = sum_{k in chunk} h[b][k] W_hh[c][k]
// grid (16 c-tiles of 256, 8 k-chunks of 128), 256 threads, thread = 4b x 8c.
__global__ void lstm_gemm(int t, const float* __restrict__ Whh) {
    __shared__ float Hs[32][36];
    __shared__ float Ws[32][268];
    const int tid = threadIdx.x;
    const int cBase = blockIdx.x * 256;
    const int ks = blockIdx.y;
    const int kb = ks * 128;
    const float* __restrict__ hin = g_hbuf[t & 1];
    const int b0 = (tid & 7) * 4;
    const int c0 = (tid >> 3) * 8;
    const int hb = tid >> 3, hk4 = (tid & 7) * 4;
    float acc[4][8] = {};
    for (int k0 = 0; k0 < 128; k0 += 32) {
        float4 hv = *(const float4*)&hin[hb * HH + kb + k0 + hk4];
        Hs[hk4 + 0][hb] = hv.x; Hs[hk4 + 1][hb] = hv.y;
        Hs[hk4 + 2][hb] = hv.z; Hs[hk4 + 3][hb] = hv.w;
#pragma unroll
        for (int i = 0; i < 8; i++) {
            int v = tid + i * 256;
            int c = v >> 3, k4 = (v & 7) * 4;
            float4 wv = *(const float4*)&Whh[(long)(cBase + c) * HH + kb + k0 + k4];
            Ws[k4 + 0][c] = wv.x; Ws[k4 + 1][c] = wv.y;
            Ws[k4 + 2][c] = wv.z; Ws[k4 + 3][c] = wv.w;
        }
        __syncthreads();
#pragma unroll
        for (int k = 0; k < 32; k++) {
            float4 h4 = *(const float4*)&Hs[k][b0];
            float4 wlo = *(const float4*)&Ws[k][c0];
            float4 whi = *(const float4*)&Ws[k][c0 + 4];
            float hv4[4] = {h4.x, h4.y, h4.z, h4.w};
            float wv8[8] = {wlo.x, wlo.y, wlo.z, wlo.w, whi.x, whi.y, whi.z, whi.w};
#pragma unroll
            for (int i = 0; i < 4; i++)
#pragma unroll
                for (int j = 0; j < 8; j++) acc[i][j] += hv4[i] * wv8[j];
        }
        __syncthreads();
    }
    float* po = g_lpart + (long)ks * BB * G4H;
#pragma unroll
    for (int i = 0; i < 4; i++) {
        float* row = po + (long)(b0 + i) * G4H + cBase + c0;
        *(float4*)row = make_float4(acc[i][0], acc[i][1], acc[i][2], acc[i][3]);
        *(float4*)(row + 4) = make_float4(acc[i][4], acc[i][5], acc[i][6], acc[i][7]);
    }
}

// ---------------- attn_step: fused gate pointwise (h,c update) + attention ----------
__global__ void attn_step(int t, const float* __restrict__ hiddens) {
    const int b = blockIdx.x;
    __shared__ float hsh[HH];
    __shared__ float sc[SS];
    const int tid = threadIdx.x;
    const int lane = tid & 31, w = tid >> 5;
    // phase 0: gates -> h, c
    const float* gi = g_gi + (long)(t * BB + b) * G4H;
    float* hout = g_hbuf[(t + 1) & 1];
    for (int jj = tid; jj < HH; jj += 512) {
        float xi = gi[jj], xf = gi[HH + jj], xg = gi[2 * HH + jj], xo = gi[3 * HH + jj];
#pragma unroll
        for (int ks = 0; ks < KSL; ks++) {
            const float* p = g_lpart + (long)(ks * BB + b) * G4H;
            xi += p[jj]; xf += p[HH + jj]; xg += p[2 * HH + jj]; xo += p[3 * HH + jj];
        }
        float ig = 1.f / (1.f + expf(-xi));
        float fg = 1.f / (1.f + expf(-xf));
        float gg = tanhf(xg);
        float og = 1.f / (1.f + expf(-xo));
        float cn = fg * g_c[b * HH + jj] + ig * gg;
        g_c[b * HH + jj] = cn;
        float hv = og * tanhf(cn);
        hsh[jj] = hv;
        hout[b * HH + jj] = hv;
    }
    __syncthreads();
    // scores: 16 warps x 4 s each
#pragma unroll
    for (int si = 0; si < 4; si++) {
        int s = si * 16 + w;
        const float* e = hiddens + ((long)s * BB + b) * HH;
        float a = 0.f;
#pragma unroll
        for (int r = 0; r < 8; r++) {
            int k = lane * 4 + r * 128;
            float4 ev = *(const float4*)&e[k];
            float4 hv = *(const float4*)&hsh[k];
            a += ev.x * hv.x + ev.y * hv.y + ev.z * hv.z + ev.w * hv.w;
        }
        for (int o = 16; o; o >>= 1) a += __shfl_down_sync(0xFFFFFFFFu, a, o);
        if (!lane) sc[s] = a;
    }
    __syncthreads();
    if (tid < 32) {
        float v0 = sc[tid], v1 = sc[tid + 32];
        float m = fmaxf(v0, v1);
        for (int o = 16; o; o >>= 1) m = fmaxf(m, __shfl_xor_sync(0xFFFFFFFFu, m, o));
        float e0 = expf(v0 - m), e1 = expf(v1 - m);
        float sm = e0 + e1;
        for (int o = 16; o; o >>= 1) sm += __shfl_xor_sync(0xFFFFFFFFu, sm, o);
        sc[tid] = e0 / sm; sc[tid + 32] = e1 / sm;
    }
    __syncthreads();
    // ctx: 2 s-groups x 256 float4-cols
    const int cc = tid & 255, sg = tid >> 8;
    const int col = cc * 4;
    float4 acc = make_float4(0.f, 0.f, 0.f, 0.f);
#pragma unroll 4
    for (int s = sg * 32; s < sg * 32 + 32; s++) {
        float a = sc[s];
        float4 e = *(const float4*)&hiddens[((long)s * BB + b) * HH + col];
        acc.x += a * e.x; acc.y += a * e.y; acc.z += a * e.z; acc.w += a * e.w;
    }
    float4* cpart = (float4*)hsh;
    if (sg == 1) cpart[cc] = acc;
    __syncthreads();
    if (sg == 0) {
        float4 o2 = cpart[cc];
        acc.x += o2.x; acc.y += o2.y; acc.z += o2.z; acc.w += o2.w;
        *(float4*)&g_ctx[b * HH + col] = acc;
    }
}

// ---------------- fc1_gemm: partial[t][ks][b][j] over K=2048 ([h|ctx]) ----------
// grid (8 c-tiles of 128, 16 k-chunks of 128), 256 threads, thread = 4b x 4c.
__global__ void fc1_gemm(int t, const float* __restrict__ W) {
    __shared__ float Hs[32][36];
    __shared__ float Ws[32][132];
    const int tid = threadIdx.x;
    const int cBase = blockIdx.x * 128;
    const int ks = blockIdx.y;
    const int kb = (ks & 7) * 128;
    const float* __restrict__ A = (ks < 8) ? g_hbuf[(t + 1) & 1] : g_ctx;
    const int b0 = (tid & 7) * 4;
    const int c0 = (tid >> 3) * 4;
    const int hb = tid >> 3, hk4 = (tid & 7) * 4;
    float acc[4][4] = {};
    for (int k0 = 0; k0 < 128; k0 += 32) {
        float4 hv = *(const float4*)&A[hb * HH + kb + k0 + hk4];
        Hs[hk4 + 0][hb] = hv.x; Hs[hk4 + 1][hb] = hv.y;
        Hs[hk4 + 2][hb] = hv.z; Hs[hk4 + 3][hb] = hv.w;
#pragma unroll
        for (int i = 0; i < 4; i++) {
            int v = tid + i * 256;
            int c = v >> 3, k4 = (v & 7) * 4;
            float4 wv = *(const float4*)&W[(long)(cBase + c) * 2048 + ks * 128 + k0 + k4];
            Ws[k4 + 0][c] = wv.x; Ws[k4 + 1][c] = wv.y;
            Ws[k4 + 2][c] = wv.z; Ws[k4 + 3][c] = wv.w;
        }
        __syncthreads();
#pragma unroll
        for (int k = 0; k < 32; k++) {
            float4 h4 = *(const float4*)&Hs[k][b0];
            float4 w4 = *(const float4*)&Ws[k][c0];
            float hv4[4] = {h4.x, h4.y, h4.z, h4.w};
            float wv4[4] = {w4.x, w4.y, w4.z, w4.w};
#pragma unroll
            for (int i = 0; i < 4; i++)
#pragma unroll
                for (int j = 0; j < 4; j++) acc[i][j] += hv4[i] * wv4[j];
        }
        __syncthreads();
    }
    float* po = g_fpart + ((long)(t * KSF + ks) * BB) * HH;
#pragma unroll
    for (int i = 0; i < 4; i++)
        *(float4*)&po[(long)(b0 + i) * HH + cBase + c0] =
            make_float4(acc[i][0], acc[i][1], acc[i][2], acc[i][3]);
}

// ---------------- fc1_point: barout = tanh(sum_ks partial + bias), once for all t ----
__global__ void fc1_point(const float* __restrict__ bias) {
    const int tb = blockIdx.x;           // t*32+b
    const int tt = tb >> 5, b = tb & 31;
    const int j = threadIdx.x * 4;
    float4 s = *(const float4*)&bias[j];
#pragma unroll
    for (int ks = 0; ks < KSF; ks++) {
        float4 p = *(const float4*)&g_fpart[((long)(tt * KSF + ks) * BB + b) * HH + j];
        s.x += p.x; s.y += p.y; s.z += p.z; s.w += p.w;
    }
    s.x = tanhf(s.x); s.y = tanhf(s.y); s.z = tanhf(s.z); s.w = tanhf(s.w);
    *(float4*)&g_barout[(long)tb * HH + j] = s;
}

// ---------------- fc2: tf32 mma.sync GEMM. M=2048, N=32000, K=1024 ----------------
__device__ __forceinline__ uint32_t f2tf(float x) {
    uint32_t r;
    asm("cvt.rna.tf32.f32 %0, %1;" : "=r"(r) : "f"(x));
    return r;
}
__device__ __forceinline__ void mma_tf32(float* c, const uint32_t* a, const uint32_t* b) {
    asm volatile(
        "mma.sync.aligned.m16n8k8.row.col.f32.tf32.tf32.f32 "
        "{%0,%1,%2,%3},{%4,%5,%6,%7},{%8,%9},{%0,%1,%2,%3};"
        : "+f"(c[0]), "+f"(c[1]), "+f"(c[2]), "+f"(c[3])
        : "r"(a[0]), "r"(a[1]), "r"(a[2]), "r"(a[3]), "r"(b[0]), "r"(b[1]));
}

__global__ void __launch_bounds__(256) fc2_mma(const float* __restrict__ Wt,
                                               const float* __restrict__ bias,
                                               float* __restrict__ out) {
    extern __shared__ float smem[];
    float* As = smem;            // [2buf][2ks][128][12] = 6144 floats
    float* Bs = smem + 6144;     // [2buf][2ks][256][12] = 12288 floats
    const int tid = threadIdx.x;
    const int wid = tid >> 5, lane = tid & 31;
    const int g = lane >> 2, kq = lane & 3;
    const int mBase = blockIdx.y * 128;
    const int nBase = blockIdx.x * 256;
    const int warpM = (wid & 1) * 64;
    const int warpN = (wid >> 1) * 64;

    float acc[4][8][4];
#pragma unroll
    for (int i = 0; i < 4; i++)
#pragma unroll
        for (int j = 0; j < 8; j++)
#pragma unroll
            for (int k = 0; k < 4; k++) acc[i][j][k] = 0.f;

    float bc0[8], bc1[8];
#pragma unroll
    for (int nf = 0; nf < 8; nf++) {
        int col = nBase + warpN + nf * 8 + kq * 2;
        bc0[nf] = bias[col]; bc1[nf] = bias[col + 1];
    }

    const int arow = tid >> 2, aq = tid & 3;   // A: rows arow, arow+64
    // prologue: tile 0 -> buf 0
    {
        const int kt = 0;
#pragma unroll
        for (int i = 0; i < 2; i++) {
            float4 v = *(const float4*)&g_barout[(long)(mBase + arow + i * 64) * HH + kt * 16 + aq * 4];
            float* d = &As[((0 * 2 + (aq >> 1)) * 128 + arow + i * 64) * 12 + (aq & 1) * 4];
            d[0] = __uint_as_float(f2tf(v.x)); d[1] = __uint_as_float(f2tf(v.y));
            d[2] = __uint_as_float(f2tf(v.z)); d[3] = __uint_as_float(f2tf(v.w));
        }
#pragma unroll
        for (int i = 0; i < 4; i++) {
            float4 v = *(const float4*)&Wt[(long)(nBase + arow + i * 64) * HH + kt * 16 + aq * 4];
            float* d = &Bs[((0 * 2 + (aq >> 1)) * 256 + arow + i * 64) * 12 + (aq & 1) * 4];
            d[0] = __uint_as_float(f2tf(v.x)); d[1] = __uint_as_float(f2tf(v.y));
            d[2] = __uint_as_float(f2tf(v.z)); d[3] = __uint_as_float(f2tf(v.w));
        }
    }
    __syncthreads();

    float4 ra[2], rb[4];
    for (int kt = 0; kt < 64; kt++) {
        const int cur = kt & 1;
        if (kt < 63) {
#pragma unroll
            for (int i = 0; i < 2; i++)
                ra[i] = *(const float4*)&g_barout[(long)(mBase + arow + i * 64) * HH + (kt + 1) * 16 + aq * 4];
#pragma unroll
            for (int i = 0; i < 4; i++)
                rb[i] = *(const float4*)&Wt[(long)(nBase + arow + i * 64) * HH + (kt + 1) * 16 + aq * 4];
        }
        // compute on buf cur
#pragma unroll
        for (int ksx = 0; ksx < 2; ksx++) {
            const float* Ab = As + ((cur * 2 + ksx) * 128) * 12;
            const float* Bb = Bs + ((cur * 2 + ksx) * 256) * 12;
            uint32_t bfr[8][2];
#pragma unroll
            for (int nf = 0; nf < 8; nf++) {
                int n = warpN + nf * 8 + g;
                bfr[nf][0] = __float_as_uint(Bb[n * 12 + kq]);
                bfr[nf][1] = __float_as_uint(Bb[n * 12 + kq + 4]);
            }
#pragma unroll
            for (int mf = 0; mf < 4; mf++) {
                int r = warpM + mf * 16 + g;
                uint32_t a[4];
                a[0] = __float_as_uint(Ab[r * 12 + kq]);
                a[1] = __float_as_uint(Ab[(r + 8) * 12 + kq]);
                a[2] = __float_as_uint(Ab[r * 12 + kq + 4]);
                a[3] = __float_as_uint(Ab[(r + 8) * 12 + kq + 4]);
#pragma unroll
                for (int nf = 0; nf < 8; nf++) mma_tf32(acc[mf][nf], a, bfr[nf]);
            }
        }
        if (kt < 63) {
            const int nxt = cur ^ 1;
#pragma unroll
            for (int i = 0; i < 2; i++) {
                float* d = &As[((nxt * 2 + (aq >> 1)) * 128 + arow + i * 64) * 12 + (aq & 1) * 4];
                d[0] = __uint_as_float(f2tf(ra[i].x)); d[1] = __uint_as_float(f2tf(ra[i].y));
                d[2] = __uint_as_float(f2tf(ra[i].z)); d[3] = __uint_as_float(f2tf(ra[i].w));
            }
#pragma unroll
            for (int i = 0; i < 4; i++) {
                float* d = &Bs[((nxt * 2 + (aq >> 1)) * 256 + arow + i * 64) * 12 + (aq & 1) * 4];
                d[0] = __uint_as_float(f2tf(rb[i].x)); d[1] = __uint_as_float(f2tf(rb[i].y));
                d[2] = __uint_as_float(f2tf(rb[i].z)); d[3] = __uint_as_float(f2tf(rb[i].w));
            }
        }
        __syncthreads();
    }

    // epilogue
#pragma unroll
    for (int mf = 0; mf < 4; mf++) {
        int r0 = mBase + warpM + mf * 16 + g;
        int r1 = r0 + 8;
        int t0 = r0 >> 5, b0i = r0 & 31;
        int t1 = r1 >> 5, b1i = r1 & 31;
#pragma unroll
        for (int nf = 0; nf < 8; nf++) {
            int col = nBase + warpN + nf * 8 + kq * 2;
            float2 v0 = make_float2(acc[mf][nf][0] + bc0[nf], acc[mf][nf][1] + bc1[nf]);
            float2 v1 = make_float2(acc[mf][nf][2] + bc0[nf], acc[mf][nf][3] + bc1[nf]);
            *(float2*)&out[((long)b0i * TT + t0) * VV + col] = v0;
            *(float2*)&out[((long)b1i * TT + t1) * VV + col] = v1;
        }
    }
}

// ---------------- launch ----------------
extern "C" void kernel_launch(void* const* d_in, const int* in_sizes, int n_in,
                              void* d_out, int out_size) {
    const int*   inputs  = (const int*)d_in[0];
    const float* hiddens = (const float*)d_in[1];
    const float* hidden  = (const float*)d_in[2];
    const float* cell    = (const float*)d_in[3];
    const float* emb     = (const float*)d_in[4];
    const float* W_ih    = (const float*)d_in[5];
    const float* b_ih    = (const float*)d_in[6];
    const float* W_hh    = (const float*)d_in[7];
    const float* b_hh    = (const float*)d_in[8];
    const float* fc1_W   = (const float*)d_in[9];
    const float* fc1_b   = (const float*)d_in[10];
    const float* fc2_W   = (const float*)d_in[11];
    const float* fc2_b   = (const float*)d_in[12];
    float* out = (float*)d_out;

    cudaFuncSetAttribute(fc2_mma, cudaFuncAttributeMaxDynamicSharedMemorySize, 73728);

    init_hc<<<128, 256>>>(hidden, cell);
    embed_gemm<<<dim3(G4H / 128, (TT * BB) / 128), 256>>>(inputs, emb, W_ih, b_ih, b_hh);
    for (int t = 0; t < TT; t++) {
        lstm_gemm<<<dim3(16, 8), 256>>>(t, W_hh);
        attn_step<<<BB, 512>>>(t, hiddens);
        fc1_gemm<<<dim3(8, 16), 256>>>(t, fc1_W);
    }
    fc1_point<<<TT * BB, 256>>>(fc1_b);
    fc2_mma<<<dim3(VV / 256, (TT * BB) / 128), 256, 73728>>>(fc2_W, fc2_b, out);
}